// round 14
// baseline (speedup 1.0000x reference)
#include <cuda_runtime.h>
#include <cuda_fp16.h>
#include <math.h>
#include <stdint.h>

#define BATCH   2
#define SEQL    2048
#define EMBED   1024
#define HEADS   16
#define HDIM    64
#define M_TOTAL (BATCH*SEQL)   /* 4096 */
#define QKV_N   (3*EMBED)      /* 3072 */

// Scratch (alloc-free rule: __device__ globals)
__device__ __half g_qkv [M_TOTAL * (size_t)QKV_N];
__device__ __half g_attn[M_TOTAL * (size_t)EMBED];

// ---------------------------------------------------------------------------
__device__ __forceinline__ uint32_t h2b(__half2 h) { return *(uint32_t*)&h; }

__device__ __forceinline__ void mma_f16(float c[4],
    uint32_t a0, uint32_t a1, uint32_t a2, uint32_t a3,
    uint32_t b0, uint32_t b1)
{
    asm volatile(
        "mma.sync.aligned.m16n8k16.row.col.f32.f16.f16.f32 "
        "{%0,%1,%2,%3}, {%4,%5,%6,%7}, {%8,%9}, {%0,%1,%2,%3};"
        : "+f"(c[0]), "+f"(c[1]), "+f"(c[2]), "+f"(c[3])
        : "r"(a0), "r"(a1), "r"(a2), "r"(a3), "r"(b0), "r"(b1));
}

__device__ __forceinline__ void ldsm_x4(uint32_t& v0, uint32_t& v1,
                                        uint32_t& v2, uint32_t& v3,
                                        const void* p)
{
    uint32_t a = (uint32_t)__cvta_generic_to_shared(p);
    asm volatile("ldmatrix.sync.aligned.m8n8.x4.shared.b16 {%0,%1,%2,%3}, [%4];"
                 : "=r"(v0), "=r"(v1), "=r"(v2), "=r"(v3) : "r"(a));
}
__device__ __forceinline__ void ldsm_x4_t(uint32_t& v0, uint32_t& v1,
                                          uint32_t& v2, uint32_t& v3,
                                          const void* p)
{
    uint32_t a = (uint32_t)__cvta_generic_to_shared(p);
    asm volatile("ldmatrix.sync.aligned.m8n8.x4.trans.shared.b16 {%0,%1,%2,%3}, [%4];"
                 : "=r"(v0), "=r"(v1), "=r"(v2), "=r"(v3) : "r"(a));
}

// ---------------------------------------------------------------------------
// C[M,N] = A[M,K] @ B[N,K]^T (+bias), fp16 mma, fp32 accum. ldmatrix frags.
// 128x128 block tile, BK=32, 8 warps (2x4), warp tile 64x32.
// TA: float or __half input A. TC: __half (no bias) or float (+bias).
// ---------------------------------------------------------------------------
#define GST 40   /* smem row stride in halves; 80B*8 = 5*128B -> ldmatrix conflict-free */

template<typename TA, typename TC, bool HAS_BIAS>
__global__ __launch_bounds__(256)
void gemm_f16(const TA* __restrict__ A, const float* __restrict__ B,
              TC* __restrict__ C, int M, int N, int K,
              const float* __restrict__ bias)
{
    __shared__ __half As[2][128][GST];
    __shared__ __half Bs[2][128][GST];

    const int tid  = threadIdx.x;
    const int lane = tid & 31, wid = tid >> 5;
    const int g = lane >> 2, t = lane & 3;
    const int wr = wid >> 2, wc = wid & 3;
    const int bm = blockIdx.y * 128, bn = blockIdx.x * 128;
    const int lm_m = lane >> 3, lm_r = lane & 7;

    const int lrow = tid >> 3;            // 0..31
    const int lcol = (tid & 7) << 2;      // 0,4,...,28

    const TA*    Ap = A + (size_t)(bm + lrow) * K + lcol;
    const float* Bp = B + (size_t)(bn + lrow) * K + lcol;
    const size_t rstep = (size_t)32 * K;

    __half2 ra[4][2]; float4 rbf[4];
#pragma unroll
    for (int i = 0; i < 4; i++) {
        if constexpr (sizeof(TA) == 2) {
            uint2 u = *(const uint2*)(Ap + i * rstep);
            ra[i][0] = *(__half2*)&u.x;  ra[i][1] = *(__half2*)&u.y;
        } else {
            float4 v = *(const float4*)(Ap + i * rstep);
            ra[i][0] = __floats2half2_rn(v.x, v.y);
            ra[i][1] = __floats2half2_rn(v.z, v.w);
        }
        rbf[i] = *(const float4*)(Bp + i * rstep);
    }

    float acc[4][4][4];
#pragma unroll
    for (int mf = 0; mf < 4; mf++)
#pragma unroll
        for (int nf = 0; nf < 4; nf++)
#pragma unroll
            for (int i = 0; i < 4; i++) acc[mf][nf][i] = 0.f;

#pragma unroll
    for (int i = 0; i < 4; i++) {
        *(__half2*)&As[0][lrow + i*32][lcol]     = ra[i][0];
        *(__half2*)&As[0][lrow + i*32][lcol + 2] = ra[i][1];
        *(__half2*)&Bs[0][lrow + i*32][lcol]     = __floats2half2_rn(rbf[i].x, rbf[i].y);
        *(__half2*)&Bs[0][lrow + i*32][lcol + 2] = __floats2half2_rn(rbf[i].z, rbf[i].w);
    }
    __syncthreads();

    int p = 0;
    for (int kt = 0; kt < K; kt += 32) {
        const bool more = (kt + 32 < K);
        if (more) {
#pragma unroll
            for (int i = 0; i < 4; i++) {
                if constexpr (sizeof(TA) == 2) {
                    uint2 u = *(const uint2*)(Ap + (kt + 32) + i * rstep);
                    ra[i][0] = *(__half2*)&u.x;  ra[i][1] = *(__half2*)&u.y;
                } else {
                    float4 v = *(const float4*)(Ap + (kt + 32) + i * rstep);
                    ra[i][0] = __floats2half2_rn(v.x, v.y);
                    ra[i][1] = __floats2half2_rn(v.z, v.w);
                }
                rbf[i] = *(const float4*)(Bp + (kt + 32) + i * rstep);
            }
        }
#pragma unroll
        for (int ks = 0; ks < 2; ks++) {
            const int k0 = ks * 16;
            uint32_t af[4][4], bf[4][2];
#pragma unroll
            for (int mf = 0; mf < 4; mf++) {
                ldsm_x4(af[mf][0], af[mf][1], af[mf][2], af[mf][3],
                        &As[p][wr*64 + mf*16 + (lm_m & 1)*8 + lm_r][k0 + (lm_m >> 1)*8]);
            }
#pragma unroll
            for (int nfp = 0; nfp < 2; nfp++) {
                ldsm_x4(bf[2*nfp][0], bf[2*nfp][1], bf[2*nfp+1][0], bf[2*nfp+1][1],
                        &Bs[p][wc*32 + nfp*16 + (lm_m >> 1)*8 + lm_r][k0 + (lm_m & 1)*8]);
            }
#pragma unroll
            for (int mf = 0; mf < 4; mf++)
#pragma unroll
                for (int nf = 0; nf < 4; nf++)
                    mma_f16(acc[mf][nf], af[mf][0], af[mf][1], af[mf][2], af[mf][3],
                            bf[nf][0], bf[nf][1]);
        }
        if (more) {
            const int q = p ^ 1;
#pragma unroll
            for (int i = 0; i < 4; i++) {
                *(__half2*)&As[q][lrow + i*32][lcol]     = ra[i][0];
                *(__half2*)&As[q][lrow + i*32][lcol + 2] = ra[i][1];
                *(__half2*)&Bs[q][lrow + i*32][lcol]     = __floats2half2_rn(rbf[i].x, rbf[i].y);
                *(__half2*)&Bs[q][lrow + i*32][lcol + 2] = __floats2half2_rn(rbf[i].z, rbf[i].w);
            }
            __syncthreads();
        }
        p ^= 1;
    }

#pragma unroll
    for (int mf = 0; mf < 4; mf++) {
        const int r = bm + wr*64 + mf*16 + g;
#pragma unroll
        for (int nf = 0; nf < 4; nf++) {
            const int c = bn + wc*32 + nf*8 + 2*t;
            if constexpr (sizeof(TC) == 2) {
                *(__half2*)&C[(size_t)r       * N + c] = __floats2half2_rn(acc[mf][nf][0], acc[mf][nf][1]);
                *(__half2*)&C[(size_t)(r + 8) * N + c] = __floats2half2_rn(acc[mf][nf][2], acc[mf][nf][3]);
            } else {
                float b0 = HAS_BIAS ? bias[c]     : 0.f;
                float b1 = HAS_BIAS ? bias[c + 1] : 0.f;
                *(float2*)&C[(size_t)r       * N + c] = make_float2(acc[mf][nf][0] + b0, acc[mf][nf][1] + b1);
                *(float2*)&C[(size_t)(r + 8) * N + c] = make_float2(acc[mf][nf][2] + b0, acc[mf][nf][3] + b1);
            }
        }
    }
}

// ---------------------------------------------------------------------------
// Flash attention, fp16 mma, fp32 softmax (log2 domain). ldmatrix everywhere.
// 4 warps, BM=64 q, BN=64 keys/tile. Output stored as half.
// ---------------------------------------------------------------------------
#define AST 72   /* 144B*8 = 9*128B -> ldmatrix conflict-free */
#define FULLM 0xffffffffu
#define SCALE_LOG2 0.180336879f   /* 0.125 * log2(e) */

__global__ __launch_bounds__(128, 4)
void attn_f16(const __half* __restrict__ qkv, const int* __restrict__ mask,
              __half* __restrict__ out)
{
    __shared__ __half Qh[64][AST];
    __shared__ __half Kh[64][AST];
    __shared__ __half Vh[64][AST];
    __shared__ float  maskadd[64];

    const int bhead = blockIdx.y;
    const int b = bhead >> 4, h = bhead & 15;
    const int q0 = blockIdx.x * 64;
    const int tid = threadIdx.x;
    const int lane = tid & 31, wid = tid >> 5;
    const int g = lane >> 2, t = lane & 3;
    const int r0 = wid * 16;
    const int lm_m = lane >> 3, lm_r = lane & 7;

    for (int i = tid; i < 64*16; i += 128) {
        const int r = i >> 4, c4 = (i & 15) << 2;
        *(uint2*)&Qh[r][c4] =
            *(const uint2*)(qkv + (size_t)(b*SEQL + q0 + r)*QKV_N + h*HDIM + c4);
    }

    float oc[8][4];
#pragma unroll
    for (int nf = 0; nf < 8; nf++)
#pragma unroll
        for (int i = 0; i < 4; i++) oc[nf][i] = 0.f;
    float m0 = -INFINITY, m1 = -INFINITY, l0 = 0.f, l1 = 0.f;

    for (int kt = 0; kt < SEQL; kt += 64) {
        __syncthreads();
        for (int i = tid; i < 64*16; i += 128) {
            const int r = i >> 4, c4 = (i & 15) << 2;
            const size_t rowbase = (size_t)(b*SEQL + kt + r)*QKV_N + h*HDIM + c4;
            *(uint2*)&Kh[r][c4] = *(const uint2*)(qkv + rowbase + EMBED);
            *(uint2*)&Vh[r][c4] = *(const uint2*)(qkv + rowbase + 2*EMBED);
        }
        if (tid < 64)
            maskadd[tid] = (mask[b*SEQL + kt + tid] == 0) ? -INFINITY : 0.f;
        __syncthreads();

        // ---- S = Q K^T (16 x 64 per warp), ldmatrix frags ----
        float sc[8][4];
#pragma unroll
        for (int nf = 0; nf < 8; nf++)
#pragma unroll
            for (int i = 0; i < 4; i++) sc[nf][i] = 0.f;
#pragma unroll
        for (int ks = 0; ks < 4; ks++) {
            const int k0 = ks * 16;
            uint32_t qa0, qa1, qa2, qa3;
            ldsm_x4(qa0, qa1, qa2, qa3,
                    &Qh[r0 + (lm_m & 1)*8 + lm_r][k0 + (lm_m >> 1)*8]);
#pragma unroll
            for (int nfp = 0; nfp < 4; nfp++) {
                uint32_t kb00, kb01, kb10, kb11;
                ldsm_x4(kb00, kb01, kb10, kb11,
                        &Kh[nfp*16 + (lm_m >> 1)*8 + lm_r][k0 + (lm_m & 1)*8]);
                mma_f16(sc[2*nfp    ], qa0, qa1, qa2, qa3, kb00, kb01);
                mma_f16(sc[2*nfp + 1], qa0, qa1, qa2, qa3, kb10, kb11);
            }
        }

        // ---- log2-domain scale + mask + row max ----
        float mx0 = -INFINITY, mx1 = -INFINITY;
#pragma unroll
        for (int nf = 0; nf < 8; nf++) {
            const float ma = maskadd[nf*8 + 2*t];
            const float mb = maskadd[nf*8 + 2*t + 1];
            sc[nf][0] = fmaf(sc[nf][0], SCALE_LOG2, ma);
            sc[nf][1] = fmaf(sc[nf][1], SCALE_LOG2, mb);
            sc[nf][2] = fmaf(sc[nf][2], SCALE_LOG2, ma);
            sc[nf][3] = fmaf(sc[nf][3], SCALE_LOG2, mb);
            mx0 = fmaxf(mx0, fmaxf(sc[nf][0], sc[nf][1]));
            mx1 = fmaxf(mx1, fmaxf(sc[nf][2], sc[nf][3]));
        }
        mx0 = fmaxf(mx0, __shfl_xor_sync(FULLM, mx0, 1));
        mx0 = fmaxf(mx0, __shfl_xor_sync(FULLM, mx0, 2));
        mx1 = fmaxf(mx1, __shfl_xor_sync(FULLM, mx1, 1));
        mx1 = fmaxf(mx1, __shfl_xor_sync(FULLM, mx1, 2));

        const float nm0 = fmaxf(m0, mx0), nm1 = fmaxf(m1, mx1);
        const float gd0 = (nm0 == -INFINITY) ? 0.f : nm0;
        const float gd1 = (nm1 == -INFINITY) ? 0.f : nm1;
        const float alpha0 = exp2f(m0 - gd0);
        const float alpha1 = exp2f(m1 - gd1);

        float rs0 = 0.f, rs1 = 0.f;
#pragma unroll
        for (int nf = 0; nf < 8; nf++) {
            sc[nf][0] = exp2f(sc[nf][0] - gd0);
            sc[nf][1] = exp2f(sc[nf][1] - gd0);
            sc[nf][2] = exp2f(sc[nf][2] - gd1);
            sc[nf][3] = exp2f(sc[nf][3] - gd1);
            rs0 += sc[nf][0] + sc[nf][1];
            rs1 += sc[nf][2] + sc[nf][3];
        }
        rs0 += __shfl_xor_sync(FULLM, rs0, 1);
        rs0 += __shfl_xor_sync(FULLM, rs0, 2);
        rs1 += __shfl_xor_sync(FULLM, rs1, 1);
        rs1 += __shfl_xor_sync(FULLM, rs1, 2);

        l0 = l0*alpha0 + rs0;  l1 = l1*alpha1 + rs1;
        m0 = nm0;  m1 = nm1;
#pragma unroll
        for (int nf = 0; nf < 8; nf++) {
            oc[nf][0] *= alpha0; oc[nf][1] *= alpha0;
            oc[nf][2] *= alpha1; oc[nf][3] *= alpha1;
        }

        // ---- P A-frags by half2 packing (layout-exact) ----
        uint32_t pa[4][4];
#pragma unroll
        for (int ks = 0; ks < 4; ks++) {
            pa[ks][0] = h2b(__floats2half2_rn(sc[2*ks    ][0], sc[2*ks    ][1]));
            pa[ks][1] = h2b(__floats2half2_rn(sc[2*ks    ][2], sc[2*ks    ][3]));
            pa[ks][2] = h2b(__floats2half2_rn(sc[2*ks + 1][0], sc[2*ks + 1][1]));
            pa[ks][3] = h2b(__floats2half2_rn(sc[2*ks + 1][2], sc[2*ks + 1][3]));
        }

        // ---- O += P V : V via ldmatrix.x4.trans ----
#pragma unroll
        for (int ks = 0; ks < 4; ks++) {
#pragma unroll
            for (int nfp = 0; nfp < 4; nfp++) {
                const int row = 16*ks + 8*(lm_m & 1) + lm_r;
                const int col = 8*(2*nfp + (lm_m >> 1));
                uint32_t v0, v1, v2, v3;
                ldsm_x4_t(v0, v1, v2, v3, &Vh[row][col]);
                mma_f16(oc[2*nfp    ], pa[ks][0], pa[ks][1], pa[ks][2], pa[ks][3], v0, v1);
                mma_f16(oc[2*nfp + 1], pa[ks][0], pa[ks][1], pa[ks][2], pa[ks][3], v2, v3);
            }
        }
    }

    // ---- normalize + write (half) ----
    const float inv0 = 1.f / l0, inv1 = 1.f / l1;
    const int row = b*SEQL + q0 + r0 + g;
#pragma unroll
    for (int nf = 0; nf < 8; nf++) {
        const int c = h*HDIM + nf*8 + 2*t;
        *(__half2*)&out[(size_t)row       * EMBED + c] = __floats2half2_rn(oc[nf][0]*inv0, oc[nf][1]*inv0);
        *(__half2*)&out[(size_t)(row + 8) * EMBED + c] = __floats2half2_rn(oc[nf][2]*inv1, oc[nf][3]*inv1);
    }
}

// ---------------------------------------------------------------------------
extern "C" void kernel_launch(void* const* d_in, const int* in_sizes, int n_in,
                              void* d_out, int out_size)
{
    const float* x     = (const float*)d_in[0];
    const int*   mask  = (const int*)  d_in[1];
    const float* qkv_w = (const float*)d_in[2];
    const float* out_w = (const float*)d_in[3];
    const float* out_b = (const float*)d_in[4];
    float* out = (float*)d_out;

    __half* qkv;  cudaGetSymbolAddress((void**)&qkv,  g_qkv);
    __half* attn; cudaGetSymbolAddress((void**)&attn, g_attn);

    // 1) QKV projection -> half
    gemm_f16<float, __half, false><<<dim3(QKV_N/128, M_TOTAL/128), 256>>>(
        x, qkv_w, qkv, M_TOTAL, QKV_N, EMBED, nullptr);

    // 2) Attention -> half
    attn_f16<<<dim3(SEQL/64, BATCH*HEADS), 128>>>(qkv, mask, attn);

    // 3) Output projection (half A, +bias) -> float
    gemm_f16<__half, float, true><<<dim3(EMBED/128, M_TOTAL/128), 256>>>(
        attn, out_w, out, M_TOTAL, EMBED, EMBED, out_b);
}